// round 6
// baseline (speedup 1.0000x reference)
#include <cuda_runtime.h>
#include <cuda_bf16.h>

// Problem constants
#define T_DIM 1024
#define B_DIM 128
#define C_DIM 256
#define L_DIM 64
#define S_DIM 129           // 2*L+1
#define BC    (B_DIM * C_DIM)
#define NEGV  (-1e30f)
#define LOG2E 1.4426950408889634f
#define LN2   0.6931471805599453f

#define NSLOT 14            // smem row ring slots
#define N_ENT_BLOCKS 1024
#define THREADS 256
#define DP_THREADS 160      // 5 warps cover 129 states (+ ghosts)

// Deterministic two-stage reduction scratch (fully overwritten every call)
__device__ float g_ent_part[N_ENT_BLOCKS];
__device__ float g_ctc_part[B_DIM];

#define CP_ASYNC_4(dst_smem_u32, src_gptr) \
    asm volatile("cp.async.ca.shared.global [%0], [%1], 4;" :: "r"(dst_smem_u32), "l"(src_gptr))
#define CP_ASYNC_COMMIT() asm volatile("cp.async.commit_group;")
#define CP_ASYNC_WAIT(n)  asm volatile("cp.async.wait_group %0;" :: "n"(n))

__device__ __forceinline__ float ex2(float x) {
    float r; asm("ex2.approx.f32 %0, %1;" : "=f"(r) : "f"(x)); return r;
}
__device__ __forceinline__ float lg2(float x) {
    float r; asm("lg2.approx.f32 %0, %1;" : "=f"(r) : "f"(x)); return r;
}
// log2-domain logsumexp of 3
__device__ __forceinline__ float lse2(float x, float y, float z) {
    float m = fmaxf(x, fmaxf(y, z));
    return m + lg2(ex2(x - m) + ex2(y - m) + ex2(z - m));
}

__global__ void __launch_bounds__(THREADS)
fused_ctc_entropy(const float* __restrict__ lp,
                  const int* __restrict__ targets,
                  const int* __restrict__ in_len,
                  const int* __restrict__ tgt_len)
{
    const int tid = threadIdx.x;

    __shared__ float rows[NSLOT][C_DIM];     // staged RAW log_prob rows (14 KB)
    __shared__ float buf[2][DP_THREADS + 8]; // [pad4 | states(+ghosts)], double buffered
    __shared__ float cap[2];
    __shared__ float red[THREADS / 32];

    if (blockIdx.x < B_DIM) {
        // ============ CTC DP block: log2-space, 2 steps per barrier ============
        const int b = blockIdx.x;
        const int s = tid;                    // state index; real for s < S_DIM

        if (tid < 4) { buf[0][tid] = NEGV; buf[1][tid] = NEGV; }  // pads

        const int* tg = targets + b * L_DIM;
        int  lab_s = 0, lab_m1 = 0, lab_m2 = 0;
        bool al_s = false, al_m1 = false, al_m2 = false;
        if (s < S_DIM && (s & 1)) {
            int j = s >> 1;
            lab_s = tg[j];
            al_s  = (j == 0) || (lab_s != tg[j - 1]);
        }
        if (s >= 1 && (s - 1) < S_DIM && ((s - 1) & 1)) {
            int j = (s - 1) >> 1;
            lab_m1 = tg[j];
            al_m1  = (j == 0) || (lab_m1 != tg[j - 1]);
        }
        if (s >= 2 && (s - 2) < S_DIM && ((s - 2) & 1)) {
            int j = (s - 2) >> 1;
            lab_m2 = tg[j];
            al_m2  = (j == 0) || (lab_m2 != tg[j - 1]);
        }

        const int Tlen = in_len[b];           // in [T/2, T]
        const int tl   = tgt_len[b];
        const float* rowbase = lp + b * C_DIM;

        // t = 0 init (log2 units)
        float a = NEGV;
        if (s <= 1) a = rowbase[lab_s] * LOG2E;

        // Prime pipeline: 6 groups x 2 rows (rows 1..12)
        #pragma unroll
        for (int g = 0; g < 6; ++g) {
            int r0 = 1 + 2 * g, r1 = 2 + 2 * g;
            unsigned d0 = (unsigned)__cvta_generic_to_shared(&rows[r0 % NSLOT][tid]);
            unsigned d1 = (unsigned)__cvta_generic_to_shared(&rows[r1 % NSLOT][tid]);
            CP_ASYNC_4(d0, rowbase + r0 * BC + tid);
            CP_ASYNC_4(d1, rowbase + r1 * BC + tid);
            CP_ASYNC_COMMIT();
        }

        __syncthreads();   // pads visible

        int p = 0;
        int t = 1;
        while (t + 1 < Tlen) {               // fused steps t and t+1
            if (tid < DP_THREADS) buf[p][4 + tid] = a;
            CP_ASYNC_WAIT(4);                // rows t..t+3 landed
            __syncthreads();

            // refill rows t+12, t+13 (clamped) as one group
            {
                int ra = t + 12; if (ra > T_DIM - 1) ra = T_DIM - 1;
                int rb = t + 13; if (rb > T_DIM - 1) rb = T_DIM - 1;
                unsigned d0 = (unsigned)__cvta_generic_to_shared(
                    &rows[(t + 12) % NSLOT][tid]);
                unsigned d1 = (unsigned)__cvta_generic_to_shared(
                    &rows[(t + 13) % NSLOT][tid]);
                CP_ASYNC_4(d0, rowbase + ra * BC + tid);
                CP_ASYNC_4(d1, rowbase + rb * BC + tid);
                CP_ASYNC_COMMIT();
            }

            if (tid < DP_THREADS) {
                const float* rt  = rows[t % NSLOT];
                const float* rt1 = rows[(t + 1) % NSLOT];
                float h1 = buf[p][3 + tid];   // a_{s-1}
                float h2 = buf[p][2 + tid];   // a_{s-2}
                float h3 = buf[p][1 + tid];   // a_{s-3}
                float h4 = buf[p][0 + tid];   // a_{s-4}

                // step t: b_s for own state
                float b_s = lse2(a, h1, al_s ? h2 : NEGV) + rt[lab_s] * LOG2E;

                // neighbors' b via shuffle; lanes 0,1 recompute from halo
                float b1 = __shfl_up_sync(0xFFFFFFFFu, b_s, 1);
                float b2 = __shfl_up_sync(0xFFFFFFFFu, b_s, 2);
                if ((tid & 31) < 2) {
                    b1 = lse2(h1, h2, al_m1 ? h3 : NEGV) + rt[lab_m1] * LOG2E;
                    b2 = lse2(h2, h3, al_m2 ? h4 : NEGV) + rt[lab_m2] * LOG2E;
                }
                if (s == 0) { b1 = NEGV; b2 = NEGV; }
                if (s == 1) { b2 = NEGV; }

                // step t+1
                a = lse2(b_s, b1, al_s ? b2 : NEGV) + rt1[lab_s] * LOG2E;
            }
            p ^= 1;
            t += 2;
        }

        if (t < Tlen) {                      // single tail step t = Tlen-1
            if (tid < DP_THREADS) buf[p][4 + tid] = a;
            CP_ASYNC_WAIT(0);
            __syncthreads();
            if (tid < DP_THREADS) {
                const float* rt = rows[t % NSLOT];
                float h1 = buf[p][3 + tid];
                float h2 = buf[p][2 + tid];
                a = lse2(a, h1, al_s ? h2 : NEGV) + rt[lab_s] * LOG2E;
            }
            p ^= 1;
        }
        CP_ASYNC_WAIT(0);                    // drain

        // a holds alpha (log2) at t = Tlen-1; capture end states
        if (tid == 2 * tl)     cap[0] = a;
        if (tid == 2 * tl - 1) cap[1] = a;
        __syncthreads();

        if (tid == 0) {
            float a1 = cap[0], a0 = cap[1];
            float m  = fmaxf(a1, a0);
            float ll2v = m + lg2(ex2(a1 - m) + ex2(a0 - m));
            float nll = -(ll2v * LN2);
            g_ctc_part[b] = (nll > 1e29f) ? 0.0f : nll;   // zero_infinity
        }
    } else {
        // ================= Entropy block: sum exp(lp)*lp =================
        const int eb = blockIdx.x - B_DIM;
        const float4* v = (const float4*)lp;
        const int n4 = (T_DIM * B_DIM * C_DIM) / 4;

        float acc = 0.0f;
        for (int i = eb * THREADS + tid; i < n4; i += N_ENT_BLOCKS * THREADS) {
            float4 x = v[i];
            acc += __expf(x.x) * x.x;
            acc += __expf(x.y) * x.y;
            acc += __expf(x.z) * x.z;
            acc += __expf(x.w) * x.w;
        }

        #pragma unroll
        for (int o = 16; o > 0; o >>= 1)
            acc += __shfl_down_sync(0xFFFFFFFFu, acc, o);
        if ((tid & 31) == 0) red[tid >> 5] = acc;
        __syncthreads();
        if (tid < THREADS / 32) {
            float r = red[tid];
            #pragma unroll
            for (int o = (THREADS / 64); o > 0; o >>= 1)
                r += __shfl_down_sync(0xFFFFFFFFu, r, o);
            if (tid == 0) g_ent_part[eb] = r;
        }
    }
}

__global__ void __launch_bounds__(256)
finalize_kernel(float* __restrict__ out)
{
    const int tid = threadIdx.x;
    float acc = 0.0f;
    for (int i = tid; i < N_ENT_BLOCKS; i += 256) acc += g_ent_part[i];

    float c = (tid < B_DIM) ? g_ctc_part[tid] : 0.0f;

    __shared__ float red[8], redc[8];
    #pragma unroll
    for (int o = 16; o > 0; o >>= 1) {
        acc += __shfl_down_sync(0xFFFFFFFFu, acc, o);
        c   += __shfl_down_sync(0xFFFFFFFFu, c, o);
    }
    if ((tid & 31) == 0) { red[tid >> 5] = acc; redc[tid >> 5] = c; }
    __syncthreads();
    if (tid == 0) {
        float es = 0.0f, cs = 0.0f;
        #pragma unroll
        for (int i = 0; i < 8; ++i) { es += red[i]; cs += redc[i]; }
        float smooth   = es / (float)(T_DIM * B_DIM);
        float ctc_mean = cs / (float)B_DIM;
        out[0] = 0.9f * ctc_mean + 0.1f * smooth;
    }
}

extern "C" void kernel_launch(void* const* d_in, const int* in_sizes, int n_in,
                              void* d_out, int out_size)
{
    const float* lp      = (const float*)d_in[0];
    const int*   targets = (const int*)d_in[1];
    const int*   in_len  = (const int*)d_in[2];
    const int*   tgt_len = (const int*)d_in[3];
    float*       out     = (float*)d_out;

    fused_ctc_entropy<<<B_DIM + N_ENT_BLOCKS, THREADS>>>(lp, targets, in_len, tgt_len);
    finalize_kernel<<<1, 256>>>(out);
}

// round 9
// speedup vs baseline: 1.3433x; 1.3433x over previous
#include <cuda_runtime.h>
#include <cuda_bf16.h>

// Problem constants
#define T_DIM 1024
#define B_DIM 128
#define C_DIM 256
#define L_DIM 64
#define S_DIM 129           // 2*L+1
#define BC    (B_DIM * C_DIM)
#define NEGV  (-1e30f)
#define LOG2E 1.4426950408889634f
#define LN2   0.6931471805599453f

#define DGRP  8             // cp.async groups primed (1 row each)
#define NSLOT 12            // smem row ring slots
#define N_ENT_BLOCKS 1024
#define THREADS 256

// Deterministic two-stage reduction scratch (fully overwritten every call)
__device__ float g_ent_part[N_ENT_BLOCKS];
__device__ float g_ctc_part[B_DIM];

#define CP_ASYNC_4(dst_smem_u32, src_gptr) \
    asm volatile("cp.async.ca.shared.global [%0], [%1], 4;" :: "r"(dst_smem_u32), "l"(src_gptr))
#define CP_ASYNC_COMMIT() asm volatile("cp.async.commit_group;")
#define CP_ASYNC_WAIT(n)  asm volatile("cp.async.wait_group %0;" :: "n"(n))

__device__ __forceinline__ float ex2f(float x) {
    float r; asm("ex2.approx.f32 %0, %1;" : "=f"(r) : "f"(x)); return r;
}
__device__ __forceinline__ float lg2f(float x) {
    float r; asm("lg2.approx.f32 %0, %1;" : "=f"(r) : "f"(x)); return r;
}

__global__ void __launch_bounds__(THREADS)
fused_ctc_entropy(const float* __restrict__ lp,
                  const int* __restrict__ targets,
                  const int* __restrict__ in_len,
                  const int* __restrict__ tgt_len)
{
    const int tid = threadIdx.x;

    __shared__ float rows[NSLOT][C_DIM];   // staged RAW log_prob rows (12 KB)
    __shared__ float buf[2][S_DIM + 2];    // [pad2 | states], double buffered
    __shared__ float cap[2];
    __shared__ float red[THREADS / 32];

    if (blockIdx.x < B_DIM) {
        // ===== CTC DP block: log2-space, 4 warps (thread k -> state k+1) =====
        const int b = blockIdx.x;
        const int s = tid + 1;               // state handled by this thread (1..128)
        const bool dp = (tid < 128);

        if (tid < 2) { buf[0][tid] = NEGV; buf[1][tid] = NEGV; }  // pads

        const int* tg = targets + b * L_DIM;
        int  label  = 0;                     // blank for even states
        bool allow2 = false;
        if (dp && (s & 1)) {
            int j = s >> 1;
            label  = tg[j];
            allow2 = (j == 0) || (label != tg[j - 1]);
        }

        const int Tlen = in_len[b];          // in [T/2, T]
        const int tl   = tgt_len[b];
        const float* rowbase = lp + b * C_DIM;

        // t = 0 init (log2 units). Thread 0 also owns state 0.
        float a  = NEGV;
        float a0 = 0.0f;
        if (tid == 0) {
            a  = rowbase[label] * LOG2E;     // state 1
            a0 = rowbase[0]     * LOG2E;     // state 0 (blank)
        }

        // Prime pipeline: rows 1..DGRP, one commit group per row
        #pragma unroll
        for (int r = 1; r <= DGRP; ++r) {
            unsigned dst = (unsigned)__cvta_generic_to_shared(&rows[r % NSLOT][tid]);
            CP_ASYNC_4(dst, rowbase + r * BC + tid);
            CP_ASYNC_COMMIT();
        }

        CP_ASYNC_WAIT(6);                    // rows 1,2 landed
        __syncthreads();                     // pads + rows visible

        // prefetch step-1 label probs (log2 units), off critical path
        float pr  = dp ? rows[1 % NSLOT][label] * LOG2E : 0.0f;
        float pr0 = (tid == 0) ? rows[1 % NSLOT][0] * LOG2E : 0.0f;

        int p = 0;
        for (int t = 1; t < Tlen; ++t) {
            if (dp) {
                buf[p][2 + s] = a;
                if (tid == 0) buf[p][2] = a0;   // state 0
            }
            CP_ASYNC_WAIT(6);                // rows up to t+1 landed (all threads)
            __syncthreads();

            // refill row t+DGRP (clamped) into its slot
            {
                int tpre = t + DGRP;
                if (tpre > T_DIM - 1) tpre = T_DIM - 1;
                unsigned dst = (unsigned)__cvta_generic_to_shared(
                    &rows[(t + DGRP) % NSLOT][tid]);
                CP_ASYNC_4(dst, rowbase + tpre * BC + tid);
                CP_ASYNC_COMMIT();
            }

            if (dp) {
                float p1 = buf[p][1 + s];        // alpha_{s-1}
                float p2 = allow2 ? buf[p][s] : NEGV;
                float m  = fmaxf(a, fmaxf(p1, p2));
                a = m + lg2f(ex2f(a - m) + ex2f(p1 - m) + ex2f(p2 - m)) + pr;
                if (tid == 0) a0 += pr0;         // state 0: no predecessors

                // prefetch next step's label probs (row t+1 resident), off-chain
                const float* rnx = rows[(t + 1) % NSLOT];
                pr = rnx[label] * LOG2E;
                if (tid == 0) pr0 = rnx[0] * LOG2E;
            }
            p ^= 1;
        }
        CP_ASYNC_WAIT(0);                    // drain before exit

        // a holds alpha (log2) at t = Tlen-1 for state tid+1; capture end states
        if (tid == 2 * tl - 1) cap[0] = a;   // state 2*tl
        if (tid == 2 * tl - 2) cap[1] = a;   // state 2*tl-1
        __syncthreads();

        if (tid == 0) {
            float a1 = cap[0], ae = cap[1];
            float m  = fmaxf(a1, ae);
            float ll2v = m + lg2f(ex2f(a1 - m) + ex2f(ae - m));
            float nll = -(ll2v * LN2);
            g_ctc_part[b] = (nll > 1e29f) ? 0.0f : nll;   // zero_infinity
        }
    } else {
        // ================= Entropy block: sum exp(lp)*lp =================
        const int eb = blockIdx.x - B_DIM;
        const float4* v = (const float4*)lp;
        const int n4 = (T_DIM * B_DIM * C_DIM) / 4;

        float acc = 0.0f;
        for (int i = eb * THREADS + tid; i < n4; i += N_ENT_BLOCKS * THREADS) {
            float4 x = v[i];
            acc += __expf(x.x) * x.x;
            acc += __expf(x.y) * x.y;
            acc += __expf(x.z) * x.z;
            acc += __expf(x.w) * x.w;
        }

        #pragma unroll
        for (int o = 16; o > 0; o >>= 1)
            acc += __shfl_down_sync(0xFFFFFFFFu, acc, o);
        if ((tid & 31) == 0) red[tid >> 5] = acc;
        __syncthreads();
        if (tid < THREADS / 32) {
            float r = red[tid];
            #pragma unroll
            for (int o = (THREADS / 64); o > 0; o >>= 1)
                r += __shfl_down_sync(0xFFFFFFFFu, r, o);
            if (tid == 0) g_ent_part[eb] = r;
        }
    }
}

__global__ void __launch_bounds__(256)
finalize_kernel(float* __restrict__ out)
{
    const int tid = threadIdx.x;
    float acc = 0.0f;
    for (int i = tid; i < N_ENT_BLOCKS; i += 256) acc += g_ent_part[i];

    float c = (tid < B_DIM) ? g_ctc_part[tid] : 0.0f;

    __shared__ float red[8], redc[8];
    #pragma unroll
    for (int o = 16; o > 0; o >>= 1) {
        acc += __shfl_down_sync(0xFFFFFFFFu, acc, o);
        c   += __shfl_down_sync(0xFFFFFFFFu, c, o);
    }
    if ((tid & 31) == 0) { red[tid >> 5] = acc; redc[tid >> 5] = c; }
    __syncthreads();
    if (tid == 0) {
        float es = 0.0f, cs = 0.0f;
        #pragma unroll
        for (int i = 0; i < 8; ++i) { es += red[i]; cs += redc[i]; }
        float smooth   = es / (float)(T_DIM * B_DIM);
        float ctc_mean = cs / (float)B_DIM;
        out[0] = 0.9f * ctc_mean + 0.1f * smooth;
    }
}

extern "C" void kernel_launch(void* const* d_in, const int* in_sizes, int n_in,
                              void* d_out, int out_size)
{
    const float* lp      = (const float*)d_in[0];
    const int*   targets = (const int*)d_in[1];
    const int*   in_len  = (const int*)d_in[2];
    const int*   tgt_len = (const int*)d_in[3];
    float*       out     = (float*)d_out;

    fused_ctc_entropy<<<B_DIM + N_ENT_BLOCKS, THREADS>>>(lp, targets, in_len, tgt_len);
    finalize_kernel<<<1, 256>>>(out);
}